// round 1
// baseline (speedup 1.0000x reference)
#include <cuda_runtime.h>
#include <cuda_bf16.h>
#include <math.h>

// Problem constants
#define Bq 2
#define Hh 16
#define Ll 4096
#define Dd 64
#define BH 32            // B*H
#define NBLK 64          // nQ = nK = L/64
#define TSEL 6           // top-k selected blocks
#define SCALE 0.125f     // 1/sqrt(64)

// Scratch (static device globals; no runtime allocation)
__device__ float g_qb[BH * NBLK * Dd];
__device__ float g_kb[BH * NBLK * Dd];
__device__ int   g_lut[BH * NBLK * TSEL];
__device__ float g_kv[(size_t)BH * NBLK * Dd * Dd];   // 33.5 MB
__device__ float g_z[BH * NBLK * Dd];
__device__ float g_kvtot[BH * Dd * Dd];
__device__ float g_ztot[BH * Dd];

// ---------------------------------------------------------------------------
// K1: block means of q and k  (grid: (2048, 2), block: 64)
// ---------------------------------------------------------------------------
__global__ void k_blockmean(const float* __restrict__ q, const float* __restrict__ k) {
    int blk = blockIdx.x;                 // bh*NBLK + blockIdx within seq
    const float* src = blockIdx.y ? k : q;
    float* dst = blockIdx.y ? g_kb : g_qb;
    int d = threadIdx.x;                  // 0..63
    const float* base = src + (size_t)blk * 64 * Dd + d;
    float s = 0.f;
#pragma unroll
    for (int r = 0; r < 64; r++) s += base[r * Dd];
    dst[blk * Dd + d] = s * (1.f / 64.f);
}

// ---------------------------------------------------------------------------
// K2: block scores + top-6 selection (grid: 2048, block: 64)
// ---------------------------------------------------------------------------
__global__ void k_topk() {
    int bh = blockIdx.x >> 6, qb = blockIdx.x & 63;
    __shared__ float qrow[Dd];
    __shared__ float sc[NBLK];
    int t = threadIdx.x;
    qrow[t] = g_qb[(bh * NBLK + qb) * Dd + t];
    __syncthreads();
    const float* kb = g_kb + (bh * NBLK + t) * Dd;
    float acc = 0.f;
#pragma unroll
    for (int d = 0; d < Dd; d++) acc += qrow[d] * kb[d];
    sc[t] = acc * SCALE;
    __syncthreads();
    if (t == 0) {
        for (int s = 0; s < TSEL; s++) {
            float best = -3.4e38f; int bi = 0;
            for (int j = 0; j < NBLK; j++)
                if (sc[j] > best) { best = sc[j]; bi = j; }  // first occurrence wins ties
            g_lut[(bh * NBLK + qb) * TSEL + s] = bi;
            sc[bi] = -3.4e38f;
        }
    }
}

// ---------------------------------------------------------------------------
// K3: per k-block  kv = phi(k)^T v  (64x64)  and  z = sum_m phi(k)
// grid: 2048, block: 256
// ---------------------------------------------------------------------------
__global__ void k_kvz(const float* __restrict__ k, const float* __restrict__ v) {
    int bh = blockIdx.x >> 6, kb = blockIdx.x & 63;
    __shared__ float ck[64 * 65];
    __shared__ float vs[64 * 65];
    int tid = threadIdx.x;
    size_t goff = ((size_t)bh * Ll + kb * 64) * Dd;
    for (int idx = tid; idx < 64 * Dd; idx += 256) {
        int r = idx >> 6, c = idx & 63;
        ck[r * 65 + c] = k[goff + idx];
        vs[r * 65 + c] = v[goff + idx];
    }
    __syncthreads();
    // row softmax of k -> phi(k)
    int warp = tid >> 5, lane = tid & 31;
    for (int r = warp; r < 64; r += 8) {
        float x0 = ck[r * 65 + lane], x1 = ck[r * 65 + lane + 32];
        float m = fmaxf(x0, x1);
#pragma unroll
        for (int o = 16; o; o >>= 1) m = fmaxf(m, __shfl_xor_sync(~0u, m, o));
        float e0 = __expf(x0 - m), e1 = __expf(x1 - m);
        float s = e0 + e1;
#pragma unroll
        for (int o = 16; o; o >>= 1) s += __shfl_xor_sync(~0u, s, o);
        float inv = 1.f / s;
        ck[r * 65 + lane] = e0 * inv;
        ck[r * 65 + lane + 32] = e1 * inv;
    }
    __syncthreads();
    // kv[d][e] = sum_m ck[m][d]*vs[m][e]   (4x4 register tile)
    int tr = tid >> 4, tc = tid & 15;
    float acc[16];
#pragma unroll
    for (int i = 0; i < 16; i++) acc[i] = 0.f;
    for (int m = 0; m < 64; m++) {
        float a[4], b[4];
#pragma unroll
        for (int i = 0; i < 4; i++) a[i] = ck[m * 65 + tr * 4 + i];
#pragma unroll
        for (int j = 0; j < 4; j++) b[j] = vs[m * 65 + tc * 4 + j];
#pragma unroll
        for (int i = 0; i < 4; i++)
#pragma unroll
            for (int j = 0; j < 4; j++) acc[i * 4 + j] += a[i] * b[j];
    }
    float* kvout = g_kv + ((size_t)(bh * NBLK + kb)) * Dd * Dd;
#pragma unroll
    for (int i = 0; i < 4; i++)
#pragma unroll
        for (int j = 0; j < 4; j++)
            kvout[(tr * 4 + i) * Dd + tc * 4 + j] = acc[i * 4 + j];
    if (tid < 64) {
        float s = 0.f;
#pragma unroll
        for (int m = 0; m < 64; m++) s += ck[m * 65 + tid];
        g_z[(bh * NBLK + kb) * Dd + tid] = s;
    }
}

// ---------------------------------------------------------------------------
// K4: totals over nK blocks (grid: 32, block: 256)
// ---------------------------------------------------------------------------
__global__ void k_totals() {
    int bh = blockIdx.x, tid = threadIdx.x;
    for (int e = tid; e < Dd * Dd; e += 256) {
        const float* p = g_kv + (size_t)bh * NBLK * Dd * Dd + e;
        float s = 0.f;
        for (int kb = 0; kb < NBLK; kb++) s += p[(size_t)kb * Dd * Dd];
        g_kvtot[bh * Dd * Dd + e] = s;
    }
    if (tid < Dd) {
        const float* p = g_z + bh * NBLK * Dd + tid;
        float s = 0.f;
        for (int kb = 0; kb < NBLK; kb++) s += p[kb * Dd];
        g_ztot[bh * Dd + tid] = s;
    }
}

// ---------------------------------------------------------------------------
// K5: fused sparse attention + linear complement + projection
// grid: 2048 (bh,qblk), block: 256, dynamic smem ~162KB
// ---------------------------------------------------------------------------
#define SPITCH 385
__global__ void __launch_bounds__(256, 1) k_main(
    const float* __restrict__ q, const float* __restrict__ k,
    const float* __restrict__ v, const float* __restrict__ W,
    const float* __restrict__ b, float* __restrict__ out)
{
    extern __shared__ float sm[];
    float* qs   = sm;                    // 64*65, q then c_q
    float* S    = qs + 64 * 65;          // 64*SPITCH
    float* buf  = S + 64 * SPITCH;       // 64*65, k/v staging
    float* kvns = buf + 64 * 65;         // 64*65
    float* Wl   = kvns + 64 * 65;        // 64*65
    float* zns  = Wl + 64 * 65;          // 64
    float* bl   = zns + 64;              // 64
    float* den  = bl + 64;               // 64
    __shared__ int lut[TSEL];

    int tid = threadIdx.x;
    int bh = blockIdx.x >> 6, qb = blockIdx.x & 63;
    size_t qoff = ((size_t)bh * Ll + qb * 64) * Dd;

    for (int idx = tid; idx < 64 * Dd; idx += 256) {
        int r = idx >> 6, c = idx & 63;
        qs[r * 65 + c] = q[qoff + idx];
        Wl[r * 65 + c] = W[idx];
    }
    if (tid < 64) bl[tid] = b[tid];
    if (tid < TSEL) lut[tid] = g_lut[(bh * NBLK + qb) * TSEL + tid];
    __syncthreads();

    int tr = tid >> 4, tc = tid & 15;
    int warp = tid >> 5, lane = tid & 31;

    // ---- S = Q K_sel^T * scale ----
    for (int t = 0; t < TSEL; t++) {
        size_t koff = ((size_t)bh * Ll + lut[t] * 64) * Dd;
        for (int idx = tid; idx < 64 * Dd; idx += 256) {
            int r = idx >> 6, c = idx & 63;
            buf[r * 65 + c] = k[koff + idx];
        }
        __syncthreads();
        float acc[16];
#pragma unroll
        for (int i = 0; i < 16; i++) acc[i] = 0.f;
#pragma unroll 4
        for (int d = 0; d < Dd; d++) {
            float a[4], bb[4];
#pragma unroll
            for (int i = 0; i < 4; i++) a[i] = qs[(tr * 4 + i) * 65 + d];
#pragma unroll
            for (int j = 0; j < 4; j++) bb[j] = buf[(tc * 4 + j) * 65 + d];
#pragma unroll
            for (int i = 0; i < 4; i++)
#pragma unroll
                for (int j = 0; j < 4; j++) acc[i * 4 + j] += a[i] * bb[j];
        }
#pragma unroll
        for (int i = 0; i < 4; i++)
#pragma unroll
            for (int j = 0; j < 4; j++)
                S[(tr * 4 + i) * SPITCH + t * 64 + tc * 4 + j] = acc[i * 4 + j] * SCALE;
        __syncthreads();
    }

    // ---- row softmax over 384 keys (warp per row) ----
    for (int r = warp; r < 64; r += 8) {
        float x[12]; float m = -3.4e38f;
#pragma unroll
        for (int j = 0; j < 12; j++) { x[j] = S[r * SPITCH + j * 32 + lane]; m = fmaxf(m, x[j]); }
#pragma unroll
        for (int o = 16; o; o >>= 1) m = fmaxf(m, __shfl_xor_sync(~0u, m, o));
        float s = 0.f;
#pragma unroll
        for (int j = 0; j < 12; j++) { x[j] = __expf(x[j] - m); s += x[j]; }
#pragma unroll
        for (int o = 16; o; o >>= 1) s += __shfl_xor_sync(~0u, s, o);
        float inv = 1.f / s;
#pragma unroll
        for (int j = 0; j < 12; j++) S[r * SPITCH + j * 32 + lane] = x[j] * inv;
    }
    __syncthreads();

    // ---- o_s = P V_sel ----
    float o_s[16];
#pragma unroll
    for (int i = 0; i < 16; i++) o_s[i] = 0.f;
    for (int t = 0; t < TSEL; t++) {
        size_t voff = ((size_t)bh * Ll + lut[t] * 64) * Dd;
        for (int idx = tid; idx < 64 * Dd; idx += 256) {
            int r = idx >> 6, c = idx & 63;
            buf[r * 65 + c] = v[voff + idx];
        }
        __syncthreads();
#pragma unroll 4
        for (int m = 0; m < 64; m++) {
            float p[4], vv[4];
#pragma unroll
            for (int i = 0; i < 4; i++) p[i] = S[(tr * 4 + i) * SPITCH + t * 64 + m];
#pragma unroll
            for (int j = 0; j < 4; j++) vv[j] = buf[m * 65 + tc * 4 + j];
#pragma unroll
            for (int i = 0; i < 4; i++)
#pragma unroll
                for (int j = 0; j < 4; j++) o_s[i * 4 + j] += p[i] * vv[j];
        }
        __syncthreads();
    }

    // ---- c_q = softmax(q) over D, in-place in qs ----
    for (int r = warp; r < 64; r += 8) {
        float x0 = qs[r * 65 + lane], x1 = qs[r * 65 + lane + 32];
        float m = fmaxf(x0, x1);
#pragma unroll
        for (int o = 16; o; o >>= 1) m = fmaxf(m, __shfl_xor_sync(~0u, m, o));
        float e0 = __expf(x0 - m), e1 = __expf(x1 - m);
        float s = e0 + e1;
#pragma unroll
        for (int o = 16; o; o >>= 1) s += __shfl_xor_sync(~0u, s, o);
        float inv = 1.f / s;
        qs[r * 65 + lane] = e0 * inv;
        qs[r * 65 + lane + 32] = e1 * inv;
    }

    // ---- kv_ns = kv_total - sum_selected ; z_ns likewise ----
    {
        const float* kvt = g_kvtot + bh * Dd * Dd;
        for (int idx = tid; idx < Dd * Dd; idx += 256) {
            float s = kvt[idx];
#pragma unroll
            for (int t = 0; t < TSEL; t++)
                s -= g_kv[((size_t)(bh * NBLK + lut[t])) * Dd * Dd + idx];
            kvns[(idx >> 6) * 65 + (idx & 63)] = s;
        }
        if (tid < 64) {
            float s = g_ztot[bh * Dd + tid];
#pragma unroll
            for (int t = 0; t < TSEL; t++)
                s -= g_z[(bh * NBLK + lut[t]) * Dd + tid];
            zns[tid] = s;
        }
    }
    __syncthreads();

    // ---- den[row] = c_q . z_ns ----
    if (tid < 64) {
        float s = 0.f;
#pragma unroll
        for (int d = 0; d < Dd; d++) s += qs[tid * 65 + d] * zns[d];
        den[tid] = s;
    }
    __syncthreads();

    // ---- o_l = (c_q kv_ns) / (den + 1e-6), stored in S region (pitch 65) ----
    float* olb = S;
    {
        float acc[16];
#pragma unroll
        for (int i = 0; i < 16; i++) acc[i] = 0.f;
#pragma unroll 4
        for (int d = 0; d < Dd; d++) {
            float a[4], bb[4];
#pragma unroll
            for (int i = 0; i < 4; i++) a[i] = qs[(tr * 4 + i) * 65 + d];
#pragma unroll
            for (int j = 0; j < 4; j++) bb[j] = kvns[d * 65 + tc * 4 + j];
#pragma unroll
            for (int i = 0; i < 4; i++)
#pragma unroll
                for (int j = 0; j < 4; j++) acc[i * 4 + j] += a[i] * bb[j];
        }
#pragma unroll
        for (int i = 0; i < 4; i++) {
            float inv = 1.f / (den[tr * 4 + i] + 1e-6f);
#pragma unroll
            for (int j = 0; j < 4; j++)
                olb[(tr * 4 + i) * 65 + tc * 4 + j] = acc[i * 4 + j] * inv;
        }
    }
    __syncthreads();

    // ---- out = o_s + o_l W^T + b ----
    {
        float acc[16];
#pragma unroll
        for (int i = 0; i < 16; i++) acc[i] = 0.f;
#pragma unroll 4
        for (int d = 0; d < Dd; d++) {
            float a[4], bb[4];
#pragma unroll
            for (int i = 0; i < 4; i++) a[i] = olb[(tr * 4 + i) * 65 + d];
#pragma unroll
            for (int j = 0; j < 4; j++) bb[j] = Wl[(tc * 4 + j) * 65 + d];
#pragma unroll
            for (int i = 0; i < 4; i++)
#pragma unroll
                for (int j = 0; j < 4; j++) acc[i * 4 + j] += a[i] * bb[j];
        }
#pragma unroll
        for (int i = 0; i < 4; i++)
#pragma unroll
            for (int j = 0; j < 4; j++) {
                int r = tr * 4 + i, c = tc * 4 + j;
                out[qoff + r * Dd + c] = o_s[i * 4 + j] + acc[i * 4 + j] + bl[c];
            }
    }
}

// ---------------------------------------------------------------------------
extern "C" void kernel_launch(void* const* d_in, const int* in_sizes, int n_in,
                              void* d_out, int out_size) {
    const float* q  = (const float*)d_in[0];
    const float* k  = (const float*)d_in[1];
    const float* v  = (const float*)d_in[2];
    const float* W  = (const float*)d_in[3];
    const float* b  = (const float*)d_in[4];
    float* out = (float*)d_out;

    int smem_main = (64 * 65 * 4 + 64 * SPITCH + 64 * 3) * (int)sizeof(float);
    cudaFuncSetAttribute(k_main, cudaFuncAttributeMaxDynamicSharedMemorySize, smem_main);

    dim3 g1(BH * NBLK, 2);
    k_blockmean<<<g1, 64>>>(q, k);
    k_topk<<<BH * NBLK, 64>>>();
    k_kvz<<<BH * NBLK, 256>>>(k, v);
    k_totals<<<BH, 256>>>();
    k_main<<<BH * NBLK, 256, smem_main>>>(q, k, v, W, b, out);
}

// round 3
// speedup vs baseline: 1.2279x; 1.2279x over previous
#include <cuda_runtime.h>
#include <cuda_bf16.h>
#include <math.h>

#define Bq 2
#define Hh 16
#define Ll 4096
#define Dd 64
#define BH 32
#define NBLK 64
#define TSEL 6
#define SCALE 0.125f
#define P68 68

__device__ float g_qb[BH * NBLK * Dd];
__device__ float g_kb[BH * NBLK * Dd];
__device__ int   g_lut[BH * NBLK * TSEL];
__device__ float g_kv[(size_t)BH * NBLK * Dd * Dd];
__device__ float g_z[BH * NBLK * Dd];
__device__ float g_kvtot[BH * Dd * Dd];
__device__ float g_ztot[BH * Dd];

// ---------------------------------------------------------------------------
__global__ void k_blockmean(const float* __restrict__ q, const float* __restrict__ k) {
    int blk = blockIdx.x;
    const float* src = blockIdx.y ? k : q;
    float* dst = blockIdx.y ? g_kb : g_qb;
    int d = threadIdx.x;
    const float* base = src + (size_t)blk * 64 * Dd + d;
    float s = 0.f;
#pragma unroll
    for (int r = 0; r < 64; r++) s += base[r * Dd];
    dst[blk * Dd + d] = s * (1.f / 64.f);
}

// ---------------------------------------------------------------------------
__global__ void k_topk() {
    int bh = blockIdx.x >> 6, qb = blockIdx.x & 63;
    __shared__ float qrow[Dd];
    __shared__ float sc[NBLK];
    int t = threadIdx.x;
    qrow[t] = g_qb[(bh * NBLK + qb) * Dd + t];
    __syncthreads();
    const float* kb = g_kb + (bh * NBLK + t) * Dd;
    float acc = 0.f;
#pragma unroll
    for (int d = 0; d < Dd; d++) acc += qrow[d] * kb[d];
    sc[t] = acc * SCALE;
    __syncthreads();
    if (t == 0) {
        for (int s = 0; s < TSEL; s++) {
            float best = -3.4e38f; int bi = 0;
            for (int j = 0; j < NBLK; j++)
                if (sc[j] > best) { best = sc[j]; bi = j; }
            g_lut[(bh * NBLK + qb) * TSEL + s] = bi;
            sc[bi] = -3.4e38f;
        }
    }
}

// ---------------------------------------------------------------------------
// K3: kv = phi(k)^T v  and  z = sum phi(k).  LDS.128 GEMM, natural layouts.
// ---------------------------------------------------------------------------
__global__ void __launch_bounds__(256) k_kvz(const float* __restrict__ k,
                                             const float* __restrict__ v) {
    __shared__ float ck[64 * P68];
    __shared__ float vs[64 * P68];
    int tid = threadIdx.x;
    int bh = blockIdx.x >> 6, kb = blockIdx.x & 63;
    size_t goff = ((size_t)bh * Ll + kb * 64) * Dd;
    int vm = tid >> 4, ve = (tid & 15) * 4;
#pragma unroll
    for (int p = 0; p < 4; p++) {
        int m = vm + p * 16;
        *(float4*)&ck[m * P68 + ve] = *(const float4*)&k[goff + (size_t)m * 64 + ve];
        *(float4*)&vs[m * P68 + ve] = *(const float4*)&v[goff + (size_t)m * 64 + ve];
    }
    __syncthreads();
    int warp = tid >> 5, lane = tid & 31;
    for (int r = warp; r < 64; r += 8) {
        float x0 = ck[r * P68 + lane], x1 = ck[r * P68 + lane + 32];
        float m = fmaxf(x0, x1);
#pragma unroll
        for (int o = 16; o; o >>= 1) m = fmaxf(m, __shfl_xor_sync(~0u, m, o));
        float e0 = __expf(x0 - m), e1 = __expf(x1 - m);
        float s = e0 + e1;
#pragma unroll
        for (int o = 16; o; o >>= 1) s += __shfl_xor_sync(~0u, s, o);
        float inv = 1.f / s;
        ck[r * P68 + lane] = e0 * inv;
        ck[r * P68 + lane + 32] = e1 * inv;
    }
    __syncthreads();
    int tr = tid >> 4, tc = tid & 15;
    float acc[16];
#pragma unroll
    for (int i = 0; i < 16; i++) acc[i] = 0.f;
#pragma unroll 16
    for (int m = 0; m < 64; m++) {
        float4 af = *(const float4*)&ck[m * P68 + tr * 4];
        float4 bf = *(const float4*)&vs[m * P68 + tc * 4];
        acc[0] += af.x * bf.x; acc[1] += af.x * bf.y; acc[2] += af.x * bf.z; acc[3] += af.x * bf.w;
        acc[4] += af.y * bf.x; acc[5] += af.y * bf.y; acc[6] += af.y * bf.z; acc[7] += af.y * bf.w;
        acc[8] += af.z * bf.x; acc[9] += af.z * bf.y; acc[10] += af.z * bf.z; acc[11] += af.z * bf.w;
        acc[12] += af.w * bf.x; acc[13] += af.w * bf.y; acc[14] += af.w * bf.z; acc[15] += af.w * bf.w;
    }
    float* kvout = g_kv + ((size_t)(bh * NBLK + kb)) * Dd * Dd;
#pragma unroll
    for (int i = 0; i < 4; i++)
        *(float4*)&kvout[(tr * 4 + i) * Dd + tc * 4] =
            make_float4(acc[i * 4], acc[i * 4 + 1], acc[i * 4 + 2], acc[i * 4 + 3]);
    if (tid < 64) {
        float s = 0.f;
#pragma unroll
        for (int m = 0; m < 64; m++) s += ck[m * P68 + tid];
        g_z[(bh * NBLK + kb) * Dd + tid] = s;
    }
}

// ---------------------------------------------------------------------------
// K4: totals — parallelized (grid (BH,16))
// ---------------------------------------------------------------------------
__global__ void k_totals() {
    int bh = blockIdx.x, tid = threadIdx.x;
    int e = blockIdx.y * 256 + tid;
    const float* p = g_kv + (size_t)bh * NBLK * Dd * Dd + e;
    float s = 0.f;
#pragma unroll 8
    for (int kb = 0; kb < NBLK; kb++) s += p[(size_t)kb * Dd * Dd];
    g_kvtot[bh * Dd * Dd + e] = s;
    if (blockIdx.y == 0 && tid < Dd) {
        const float* pz = g_z + bh * NBLK * Dd + tid;
        float sz = 0.f;
#pragma unroll 8
        for (int kb = 0; kb < NBLK; kb++) sz += pz[kb * Dd];
        g_ztot[bh * Dd + tid] = sz;
    }
}

// ---------------------------------------------------------------------------
// K5: fused main kernel. Online softmax, LDS.128 GEMMs, occ 2.
// smem layout (floats): qsT 4352 | KT 4352 | Vb 4352 | Pb 4352 | kvns 4352 |
//                       WT 4352 | zns 64 | bl 64 | den 64   = 26304 fl ~103KB
// ---------------------------------------------------------------------------
__global__ void __launch_bounds__(256, 2) k_main(
    const float* __restrict__ q, const float* __restrict__ k,
    const float* __restrict__ v, const float* __restrict__ W,
    const float* __restrict__ b, float* __restrict__ out)
{
    extern __shared__ float sm[];
    float* qsT  = sm;
    float* KT   = sm + 4352;
    float* Vb   = sm + 8704;
    float* Pb   = sm + 13056;
    float* kvns = sm + 17408;
    float* WT   = sm + 21760;
    float* zns  = sm + 26112;
    float* bl   = sm + 26176;
    float* den  = sm + 26240;
    __shared__ int lut[8];

    int tid = threadIdx.x;
    int bh = blockIdx.x >> 6, qb = blockIdx.x & 63;
    size_t qoff = ((size_t)bh * Ll + qb * 64) * Dd;

    if (tid < TSEL) lut[tid] = g_lut[(bh * NBLK + qb) * TSEL + tid];
    if (tid < 64) bl[tid] = b[tid];

    int dd = tid & 63, cb = (tid >> 6) * 16;
    // stage Q^T and W^T (coalesced global read, scalar transposed STS)
    {
        float rq[16], rw[16];
#pragma unroll
        for (int qq = 0; qq < 16; qq++) {
            rq[qq] = q[qoff + (size_t)(cb + qq) * 64 + dd];
            rw[qq] = W[(cb + qq) * 64 + dd];
        }
#pragma unroll
        for (int qq = 0; qq < 16; qq++) {
            qsT[dd * P68 + cb + qq] = rq[qq];
            WT[dd * P68 + cb + qq] = rw[qq];
        }
    }
    __syncthreads();   // lut visible
    // stage K_0^T
    {
        size_t ko = ((size_t)bh * Ll + lut[0] * 64) * Dd;
        float kr[16];
#pragma unroll
        for (int qq = 0; qq < 16; qq++) kr[qq] = k[ko + (size_t)(cb + qq) * 64 + dd];
#pragma unroll
        for (int qq = 0; qq < 16; qq++) KT[dd * P68 + cb + qq] = kr[qq];
    }
    __syncthreads();

    int tr = tid >> 4, tc = tid & 15;
    int vm = tid >> 4, ve = (tid & 15) * 4;

    float o_s[16];
    float mrow[4], lrow[4];
#pragma unroll
    for (int i = 0; i < 16; i++) o_s[i] = 0.f;
#pragma unroll
    for (int i = 0; i < 4; i++) { mrow[i] = -3.4e38f; lrow[i] = 0.f; }

    for (int t = 0; t < TSEL; t++) {
        // prefetch V_t (natural layout)
        float4 vreg[4];
        size_t vo = ((size_t)bh * Ll + lut[t] * 64) * Dd;
#pragma unroll
        for (int p = 0; p < 4; p++)
            vreg[p] = *(const float4*)&v[vo + (size_t)(vm + p * 16) * 64 + ve];

        // ---- S = Q K^T ----
        float acc[16];
#pragma unroll
        for (int i = 0; i < 16; i++) acc[i] = 0.f;
#pragma unroll 16
        for (int d = 0; d < 64; d++) {
            float4 af = *(const float4*)&qsT[d * P68 + tr * 4];
            float4 bf = *(const float4*)&KT[d * P68 + tc * 4];
            acc[0] += af.x * bf.x; acc[1] += af.x * bf.y; acc[2] += af.x * bf.z; acc[3] += af.x * bf.w;
            acc[4] += af.y * bf.x; acc[5] += af.y * bf.y; acc[6] += af.y * bf.z; acc[7] += af.y * bf.w;
            acc[8] += af.z * bf.x; acc[9] += af.z * bf.y; acc[10] += af.z * bf.z; acc[11] += af.z * bf.w;
            acc[12] += af.w * bf.x; acc[13] += af.w * bf.y; acc[14] += af.w * bf.z; acc[15] += af.w * bf.w;
        }

        // ---- online softmax update (16-lane groups share a row set) ----
        float pt[16];
#pragma unroll
        for (int i = 0; i < 4; i++) {
            float rm = fmaxf(fmaxf(acc[i * 4], acc[i * 4 + 1]),
                             fmaxf(acc[i * 4 + 2], acc[i * 4 + 3])) * SCALE;
#pragma unroll
            for (int o = 8; o; o >>= 1) rm = fmaxf(rm, __shfl_xor_sync(0xffffffffu, rm, o));
            float mn = fmaxf(mrow[i], rm);
            float corr = __expf(mrow[i] - mn);
            float rs = 0.f;
#pragma unroll
            for (int j = 0; j < 4; j++) {
                float e = __expf(acc[i * 4 + j] * SCALE - mn);
                pt[i * 4 + j] = e; rs += e;
            }
#pragma unroll
            for (int o = 8; o; o >>= 1) rs += __shfl_xor_sync(0xffffffffu, rs, o);
            lrow[i] = lrow[i] * corr + rs;
            mrow[i] = mn;
#pragma unroll
            for (int j = 0; j < 4; j++) o_s[i * 4 + j] *= corr;
        }

        // store V (natural) and P~ (transposed [m][r])
#pragma unroll
        for (int p = 0; p < 4; p++)
            *(float4*)&Vb[(vm + p * 16) * P68 + ve] = vreg[p];
#pragma unroll
        for (int j = 0; j < 4; j++)
            *(float4*)&Pb[(tc * 4 + j) * P68 + tr * 4] =
                make_float4(pt[j], pt[4 + j], pt[8 + j], pt[12 + j]);
        __syncthreads();

        // prefetch K_{t+1}
        float kr[16];
        if (t + 1 < TSEL) {
            size_t ko = ((size_t)bh * Ll + lut[t + 1] * 64) * Dd;
#pragma unroll
            for (int qq = 0; qq < 16; qq++) kr[qq] = k[ko + (size_t)(cb + qq) * 64 + dd];
        }

        // ---- o_s += P~ V ----
#pragma unroll 16
        for (int m = 0; m < 64; m++) {
            float4 af = *(const float4*)&Pb[m * P68 + tr * 4];
            float4 bf = *(const float4*)&Vb[m * P68 + tc * 4];
            o_s[0] += af.x * bf.x; o_s[1] += af.x * bf.y; o_s[2] += af.x * bf.z; o_s[3] += af.x * bf.w;
            o_s[4] += af.y * bf.x; o_s[5] += af.y * bf.y; o_s[6] += af.y * bf.z; o_s[7] += af.y * bf.w;
            o_s[8] += af.z * bf.x; o_s[9] += af.z * bf.y; o_s[10] += af.z * bf.z; o_s[11] += af.z * bf.w;
            o_s[12] += af.w * bf.x; o_s[13] += af.w * bf.y; o_s[14] += af.w * bf.z; o_s[15] += af.w * bf.w;
        }
        if (t + 1 < TSEL) {
#pragma unroll
            for (int qq = 0; qq < 16; qq++) KT[dd * P68 + cb + qq] = kr[qq];
        }
        __syncthreads();
    }

    // ---- c_q = softmax(q) over D (qsT in place; thread per row) ----
    if (tid < 64) {
        float mx = -3.4e38f;
#pragma unroll 8
        for (int d = 0; d < 64; d++) mx = fmaxf(mx, qsT[d * P68 + tid]);
        float s = 0.f;
#pragma unroll 8
        for (int d = 0; d < 64; d++) {
            float e = __expf(qsT[d * P68 + tid] - mx);
            qsT[d * P68 + tid] = e; s += e;
        }
        float inv = 1.f / s;
#pragma unroll 8
        for (int d = 0; d < 64; d++) qsT[d * P68 + tid] *= inv;
    }

    // ---- kv_ns, z_ns ----
    {
        int d0 = tid >> 2, e0 = (tid & 3) * 16;
        const float* kvt = g_kvtot + bh * Dd * Dd;
#pragma unroll
        for (int p = 0; p < 4; p++) {
            float4 s = *(const float4*)&kvt[d0 * 64 + e0 + p * 4];
#pragma unroll
            for (int t = 0; t < TSEL; t++) {
                const float4 x = *(const float4*)
                    &g_kv[((size_t)(bh * NBLK + lut[t])) * Dd * Dd + d0 * 64 + e0 + p * 4];
                s.x -= x.x; s.y -= x.y; s.z -= x.z; s.w -= x.w;
            }
            *(float4*)&kvns[d0 * P68 + e0 + p * 4] = s;
        }
        if (tid < 64) {
            float s = g_ztot[bh * Dd + tid];
#pragma unroll
            for (int t = 0; t < TSEL; t++) s -= g_z[(bh * NBLK + lut[t]) * Dd + tid];
            zns[tid] = s;
        }
    }
    __syncthreads();

    // ---- den ----
    if (tid < 64) {
        float s = 0.f;
#pragma unroll 8
        for (int d = 0; d < 64; d++) s += qsT[d * P68 + tid] * zns[d];
        den[tid] = s;
    }
    __syncthreads();

    // ---- o_l = (c_q kv_ns)/den, write transposed into Pb ----
    {
        float acc[16];
#pragma unroll
        for (int i = 0; i < 16; i++) acc[i] = 0.f;
#pragma unroll 16
        for (int d = 0; d < 64; d++) {
            float4 af = *(const float4*)&qsT[d * P68 + tr * 4];
            float4 bf = *(const float4*)&kvns[d * P68 + tc * 4];
            acc[0] += af.x * bf.x; acc[1] += af.x * bf.y; acc[2] += af.x * bf.z; acc[3] += af.x * bf.w;
            acc[4] += af.y * bf.x; acc[5] += af.y * bf.y; acc[6] += af.y * bf.z; acc[7] += af.y * bf.w;
            acc[8] += af.z * bf.x; acc[9] += af.z * bf.y; acc[10] += af.z * bf.z; acc[11] += af.z * bf.w;
            acc[12] += af.w * bf.x; acc[13] += af.w * bf.y; acc[14] += af.w * bf.z; acc[15] += af.w * bf.w;
        }
        float inv0 = 1.f / (den[tr * 4 + 0] + 1e-6f);
        float inv1 = 1.f / (den[tr * 4 + 1] + 1e-6f);
        float inv2 = 1.f / (den[tr * 4 + 2] + 1e-6f);
        float inv3 = 1.f / (den[tr * 4 + 3] + 1e-6f);
#pragma unroll
        for (int j = 0; j < 4; j++)
            *(float4*)&Pb[(tc * 4 + j) * P68 + tr * 4] =
                make_float4(acc[j] * inv0, acc[4 + j] * inv1, acc[8 + j] * inv2, acc[12 + j] * inv3);
    }
    __syncthreads();

    // ---- out = o_s/l + o_l W^T + b ----
    {
        float acc[16];
#pragma unroll
        for (int i = 0; i < 16; i++) acc[i] = 0.f;
#pragma unroll 16
        for (int e = 0; e < 64; e++) {
            float4 af = *(const float4*)&Pb[e * P68 + tr * 4];
            float4 bf = *(const float4*)&WT[e * P68 + tc * 4];
            acc[0] += af.x * bf.x; acc[1] += af.x * bf.y; acc[2] += af.x * bf.z; acc[3] += af.x * bf.w;
            acc[4] += af.y * bf.x; acc[5] += af.y * bf.y; acc[6] += af.y * bf.z; acc[7] += af.y * bf.w;
            acc[8] += af.z * bf.x; acc[9] += af.z * bf.y; acc[10] += af.z * bf.z; acc[11] += af.z * bf.w;
            acc[12] += af.w * bf.x; acc[13] += af.w * bf.y; acc[14] += af.w * bf.z; acc[15] += af.w * bf.w;
        }
        float b0 = bl[tc * 4], b1 = bl[tc * 4 + 1], b2 = bl[tc * 4 + 2], b3 = bl[tc * 4 + 3];
#pragma unroll
        for (int i = 0; i < 4; i++) {
            float invl = 1.f / lrow[i];
            *(float4*)&out[qoff + (size_t)(tr * 4 + i) * 64 + tc * 4] =
                make_float4(o_s[i * 4 + 0] * invl + acc[i * 4 + 0] + b0,
                            o_s[i * 4 + 1] * invl + acc[i * 4 + 1] + b1,
                            o_s[i * 4 + 2] * invl + acc[i * 4 + 2] + b2,
                            o_s[i * 4 + 3] * invl + acc[i * 4 + 3] + b3);
        }
    }
}

// ---------------------------------------------------------------------------
extern "C" void kernel_launch(void* const* d_in, const int* in_sizes, int n_in,
                              void* d_out, int out_size) {
    const float* q = (const float*)d_in[0];
    const float* k = (const float*)d_in[1];
    const float* v = (const float*)d_in[2];
    const float* W = (const float*)d_in[3];
    const float* b = (const float*)d_in[4];
    float* out = (float*)d_out;

    int smem_main = 26304 * (int)sizeof(float);
    cudaFuncSetAttribute(k_main, cudaFuncAttributeMaxDynamicSharedMemorySize, smem_main);

    dim3 g1(BH * NBLK, 2);
    k_blockmean<<<g1, 64>>>(q, k);
    k_topk<<<BH * NBLK, 64>>>();
    k_kvz<<<BH * NBLK, 256>>>(k, v);
    k_totals<<<dim3(BH, 16), 256>>>();
    k_main<<<BH * NBLK, 256, smem_main>>>(q, k, v, W, b, out);
}

// round 4
// speedup vs baseline: 2.0072x; 1.6346x over previous
#include <cuda_runtime.h>
#include <cuda_bf16.h>
#include <math.h>

#define Bq 2
#define Hh 16
#define Ll 4096
#define Dd 64
#define BH 32
#define NBLK 64
#define TSEL 6
#define SCALE 0.125f
#define P68 68

typedef unsigned long long ull;

// packed fp32x2 helpers (sm_100+; ptxas never emits these from C++)
__device__ __forceinline__ ull pack2(float x, float y) {
    ull r; asm("mov.b64 %0, {%1, %2};" : "=l"(r) : "f"(x), "f"(y)); return r;
}
__device__ __forceinline__ ull dup2(float x) {
    ull r; asm("mov.b64 %0, {%1, %1};" : "=l"(r) : "f"(x)); return r;
}
__device__ __forceinline__ void ffma2(ull& d, ull a, ull b) {
    asm("fma.rn.f32x2 %0, %1, %2, %3;" : "=l"(d) : "l"(a), "l"(b), "l"(d));
}
__device__ __forceinline__ ull mul2(ull a, ull b) {
    ull r; asm("mul.rn.f32x2 %0, %1, %2;" : "=l"(r) : "l"(a), "l"(b)); return r;
}
__device__ __forceinline__ float2 unpk(ull v) {
    float2 f; asm("mov.b64 {%0, %1}, %2;" : "=f"(f.x), "=f"(f.y) : "l"(v)); return f;
}

__device__ float g_qb[BH * NBLK * Dd];
__device__ float g_kb[BH * NBLK * Dd];
__device__ int   g_lut[BH * NBLK * TSEL];
__device__ float g_kv[(size_t)BH * NBLK * Dd * Dd];
__device__ float g_z[BH * NBLK * Dd];
__device__ float g_kvtot[BH * Dd * Dd];
__device__ float g_ztot[BH * Dd];

// 4x4-output-per-thread GEMM d-step on packed accumulators acc2[8]:
// acc2[i*2+0] = cols (c0,c1) of row i ; acc2[i*2+1] = cols (c2,c3)
#define GSTEP(Abase, Bbase, ACC)                                        \
    {                                                                   \
        float4 af = *(const float4*)(Abase);                            \
        ulonglong2 bp = *(const ulonglong2*)(Bbase);                    \
        ull a0 = dup2(af.x), a1 = dup2(af.y), a2 = dup2(af.z), a3 = dup2(af.w); \
        ffma2(ACC[0], a0, bp.x); ffma2(ACC[1], a0, bp.y);               \
        ffma2(ACC[2], a1, bp.x); ffma2(ACC[3], a1, bp.y);               \
        ffma2(ACC[4], a2, bp.x); ffma2(ACC[5], a2, bp.y);               \
        ffma2(ACC[6], a3, bp.x); ffma2(ACC[7], a3, bp.y);               \
    }

// ---------------------------------------------------------------------------
__global__ void k_blockmean(const float* __restrict__ q, const float* __restrict__ k) {
    int blk = blockIdx.x;
    const float* src = blockIdx.y ? k : q;
    float* dst = blockIdx.y ? g_kb : g_qb;
    int d = threadIdx.x;
    const float* base = src + (size_t)blk * 64 * Dd + d;
    float s = 0.f;
#pragma unroll
    for (int r = 0; r < 64; r++) s += base[r * Dd];
    dst[blk * Dd + d] = s * (1.f / 64.f);
}

// ---------------------------------------------------------------------------
__global__ void k_topk() {
    int bh = blockIdx.x >> 6, qb = blockIdx.x & 63;
    __shared__ float qrow[Dd];
    __shared__ float sc[NBLK];
    int t = threadIdx.x;
    qrow[t] = g_qb[(bh * NBLK + qb) * Dd + t];
    __syncthreads();
    const float* kb = g_kb + (bh * NBLK + t) * Dd;
    float acc = 0.f;
#pragma unroll
    for (int d = 0; d < Dd; d++) acc += qrow[d] * kb[d];
    sc[t] = acc * SCALE;
    __syncthreads();
    if (t == 0) {
        for (int s = 0; s < TSEL; s++) {
            float best = -3.4e38f; int bi = 0;
            for (int j = 0; j < NBLK; j++)
                if (sc[j] > best) { best = sc[j]; bi = j; }
            g_lut[(bh * NBLK + qb) * TSEL + s] = bi;
            sc[bi] = -3.4e38f;
        }
    }
}

// ---------------------------------------------------------------------------
__global__ void __launch_bounds__(256) k_kvz(const float* __restrict__ k,
                                             const float* __restrict__ v) {
    __shared__ float ck[64 * P68];
    __shared__ float vs[64 * P68];
    int tid = threadIdx.x;
    int bh = blockIdx.x >> 6, kb = blockIdx.x & 63;
    size_t goff = ((size_t)bh * Ll + kb * 64) * Dd;
    int vm = tid >> 4, ve = (tid & 15) * 4;
#pragma unroll
    for (int p = 0; p < 4; p++) {
        int m = vm + p * 16;
        *(float4*)&ck[m * P68 + ve] = *(const float4*)&k[goff + (size_t)m * 64 + ve];
        *(float4*)&vs[m * P68 + ve] = *(const float4*)&v[goff + (size_t)m * 64 + ve];
    }
    __syncthreads();
    int warp = tid >> 5, lane = tid & 31;
    for (int r = warp; r < 64; r += 8) {
        float x0 = ck[r * P68 + lane], x1 = ck[r * P68 + lane + 32];
        float m = fmaxf(x0, x1);
#pragma unroll
        for (int o = 16; o; o >>= 1) m = fmaxf(m, __shfl_xor_sync(~0u, m, o));
        float e0 = __expf(x0 - m), e1 = __expf(x1 - m);
        float s = e0 + e1;
#pragma unroll
        for (int o = 16; o; o >>= 1) s += __shfl_xor_sync(~0u, s, o);
        float inv = 1.f / s;
        ck[r * P68 + lane] = e0 * inv;
        ck[r * P68 + lane + 32] = e1 * inv;
    }
    __syncthreads();
    int tr = tid >> 4, tc = tid & 15;
    ull acc2[8];
#pragma unroll
    for (int i = 0; i < 8; i++) acc2[i] = 0ull;
#pragma unroll 16
    for (int m = 0; m < 64; m++)
        GSTEP(&ck[m * P68 + tr * 4], &vs[m * P68 + tc * 4], acc2);
    float* kvout = g_kv + ((size_t)(bh * NBLK + kb)) * Dd * Dd;
#pragma unroll
    for (int i = 0; i < 4; i++) {
        float2 c01 = unpk(acc2[i * 2]), c23 = unpk(acc2[i * 2 + 1]);
        *(float4*)&kvout[(tr * 4 + i) * Dd + tc * 4] =
            make_float4(c01.x, c01.y, c23.x, c23.y);
    }
    if (tid < 64) {
        float s = 0.f;
#pragma unroll
        for (int m = 0; m < 64; m++) s += ck[m * P68 + tid];
        g_z[(bh * NBLK + kb) * Dd + tid] = s;
    }
}

// ---------------------------------------------------------------------------
__global__ void k_totals() {
    int bh = blockIdx.x, tid = threadIdx.x;
    int e = blockIdx.y * 256 + tid;
    const float* p = g_kv + (size_t)bh * NBLK * Dd * Dd + e;
    float s = 0.f;
#pragma unroll 8
    for (int kb = 0; kb < NBLK; kb++) s += p[(size_t)kb * Dd * Dd];
    g_kvtot[bh * Dd * Dd + e] = s;
    if (blockIdx.y == 0 && tid < Dd) {
        const float* pz = g_z + bh * NBLK * Dd + tid;
        float sz = 0.f;
#pragma unroll 8
        for (int kb = 0; kb < NBLK; kb++) sz += pz[kb * Dd];
        g_ztot[bh * Dd + tid] = sz;
    }
}

// ---------------------------------------------------------------------------
// K5: fused main kernel. Online softmax, LDS.128 + packed FFMA2 GEMMs, occ 2.
// ---------------------------------------------------------------------------
__global__ void __launch_bounds__(256, 2) k_main(
    const float* __restrict__ q, const float* __restrict__ k,
    const float* __restrict__ v, const float* __restrict__ W,
    const float* __restrict__ b, float* __restrict__ out)
{
    extern __shared__ float sm[];
    float* qsT  = sm;
    float* KT   = sm + 4352;
    float* Vb   = sm + 8704;
    float* Pb   = sm + 13056;
    float* kvns = sm + 17408;
    float* WT   = sm + 21760;
    float* zns  = sm + 26112;
    float* bl   = sm + 26176;
    float* den  = sm + 26240;
    __shared__ int lut[8];

    int tid = threadIdx.x;
    int bh = blockIdx.x >> 6, qb = blockIdx.x & 63;
    size_t qoff = ((size_t)bh * Ll + qb * 64) * Dd;

    if (tid < TSEL) lut[tid] = g_lut[(bh * NBLK + qb) * TSEL + tid];
    if (tid < 64) bl[tid] = b[tid];

    int dd = tid & 63, cb = (tid >> 6) * 16;
    {
        float rq[16], rw[16];
#pragma unroll
        for (int qq = 0; qq < 16; qq++) {
            rq[qq] = q[qoff + (size_t)(cb + qq) * 64 + dd];
            rw[qq] = W[(cb + qq) * 64 + dd];
        }
#pragma unroll
        for (int qq = 0; qq < 16; qq++) {
            qsT[dd * P68 + cb + qq] = rq[qq];
            WT[dd * P68 + cb + qq] = rw[qq];
        }
    }
    __syncthreads();
    {
        size_t ko = ((size_t)bh * Ll + lut[0] * 64) * Dd;
        float kr[16];
#pragma unroll
        for (int qq = 0; qq < 16; qq++) kr[qq] = k[ko + (size_t)(cb + qq) * 64 + dd];
#pragma unroll
        for (int qq = 0; qq < 16; qq++) KT[dd * P68 + cb + qq] = kr[qq];
    }
    __syncthreads();

    int tr = tid >> 4, tc = tid & 15;
    int vm = tid >> 4, ve = (tid & 15) * 4;

    ull os2[8];
    float mrow[4], lrow[4];
#pragma unroll
    for (int i = 0; i < 8; i++) os2[i] = 0ull;
#pragma unroll
    for (int i = 0; i < 4; i++) { mrow[i] = -3.4e38f; lrow[i] = 0.f; }

    for (int t = 0; t < TSEL; t++) {
        float4 vreg[4];
        size_t vo = ((size_t)bh * Ll + lut[t] * 64) * Dd;
#pragma unroll
        for (int p = 0; p < 4; p++)
            vreg[p] = *(const float4*)&v[vo + (size_t)(vm + p * 16) * 64 + ve];

        // ---- S = Q K^T (packed) ----
        ull acc2[8];
#pragma unroll
        for (int i = 0; i < 8; i++) acc2[i] = 0ull;
#pragma unroll 16
        for (int d = 0; d < 64; d++)
            GSTEP(&qsT[d * P68 + tr * 4], &KT[d * P68 + tc * 4], acc2);

        // ---- online softmax update ----
        float pt[16];
#pragma unroll
        for (int i = 0; i < 4; i++) {
            float2 p01 = unpk(acc2[i * 2]), p23 = unpk(acc2[i * 2 + 1]);
            float s0 = p01.x, s1 = p01.y, s2 = p23.x, s3 = p23.y;
            float rm = fmaxf(fmaxf(s0, s1), fmaxf(s2, s3)) * SCALE;
#pragma unroll
            for (int o = 8; o; o >>= 1) rm = fmaxf(rm, __shfl_xor_sync(0xffffffffu, rm, o));
            float mn = fmaxf(mrow[i], rm);
            float corr = __expf(mrow[i] - mn);
            float e0 = __expf(s0 * SCALE - mn), e1 = __expf(s1 * SCALE - mn);
            float e2 = __expf(s2 * SCALE - mn), e3 = __expf(s3 * SCALE - mn);
            pt[i * 4 + 0] = e0; pt[i * 4 + 1] = e1; pt[i * 4 + 2] = e2; pt[i * 4 + 3] = e3;
            float rs = e0 + e1 + e2 + e3;
#pragma unroll
            for (int o = 8; o; o >>= 1) rs += __shfl_xor_sync(0xffffffffu, rs, o);
            lrow[i] = lrow[i] * corr + rs;
            mrow[i] = mn;
            ull c2 = dup2(corr);
            os2[i * 2] = mul2(os2[i * 2], c2);
            os2[i * 2 + 1] = mul2(os2[i * 2 + 1], c2);
        }

#pragma unroll
        for (int p = 0; p < 4; p++)
            *(float4*)&Vb[(vm + p * 16) * P68 + ve] = vreg[p];
#pragma unroll
        for (int j = 0; j < 4; j++)
            *(float4*)&Pb[(tc * 4 + j) * P68 + tr * 4] =
                make_float4(pt[j], pt[4 + j], pt[8 + j], pt[12 + j]);
        __syncthreads();

        float kr[16];
        if (t + 1 < TSEL) {
            size_t ko = ((size_t)bh * Ll + lut[t + 1] * 64) * Dd;
#pragma unroll
            for (int qq = 0; qq < 16; qq++) kr[qq] = k[ko + (size_t)(cb + qq) * 64 + dd];
        }

        // ---- o_s += P~ V (packed) ----
#pragma unroll 16
        for (int m = 0; m < 64; m++)
            GSTEP(&Pb[m * P68 + tr * 4], &Vb[m * P68 + tc * 4], os2);

        if (t + 1 < TSEL) {
#pragma unroll
            for (int qq = 0; qq < 16; qq++) KT[dd * P68 + cb + qq] = kr[qq];
        }
        __syncthreads();
    }

    // ---- c_q = softmax(q) over D (thread per row, in place) ----
    if (tid < 64) {
        float mx = -3.4e38f;
#pragma unroll 8
        for (int d = 0; d < 64; d++) mx = fmaxf(mx, qsT[d * P68 + tid]);
        float s = 0.f;
#pragma unroll 8
        for (int d = 0; d < 64; d++) {
            float e = __expf(qsT[d * P68 + tid] - mx);
            qsT[d * P68 + tid] = e; s += e;
        }
        float inv = 1.f / s;
#pragma unroll 8
        for (int d = 0; d < 64; d++) qsT[d * P68 + tid] *= inv;
    }

    // ---- kv_ns, z_ns ----
    {
        int d0 = tid >> 2, e0 = (tid & 3) * 16;
        const float* kvt = g_kvtot + bh * Dd * Dd;
#pragma unroll
        for (int p = 0; p < 4; p++) {
            float4 s = *(const float4*)&kvt[d0 * 64 + e0 + p * 4];
#pragma unroll
            for (int t = 0; t < TSEL; t++) {
                const float4 x = *(const float4*)
                    &g_kv[((size_t)(bh * NBLK + lut[t])) * Dd * Dd + d0 * 64 + e0 + p * 4];
                s.x -= x.x; s.y -= x.y; s.z -= x.z; s.w -= x.w;
            }
            *(float4*)&kvns[d0 * P68 + e0 + p * 4] = s;
        }
        if (tid < 64) {
            float s = g_ztot[bh * Dd + tid];
#pragma unroll
            for (int t = 0; t < TSEL; t++) s -= g_z[(bh * NBLK + lut[t]) * Dd + tid];
            zns[tid] = s;
        }
    }
    __syncthreads();

    if (tid < 64) {
        float s = 0.f;
#pragma unroll 8
        for (int d = 0; d < 64; d++) s += qsT[d * P68 + tid] * zns[d];
        den[tid] = s;
    }
    __syncthreads();

    // ---- o_l = (c_q kv_ns)/den (packed), write transposed into Pb ----
    {
        ull acc2[8];
#pragma unroll
        for (int i = 0; i < 8; i++) acc2[i] = 0ull;
#pragma unroll 16
        for (int d = 0; d < 64; d++)
            GSTEP(&qsT[d * P68 + tr * 4], &kvns[d * P68 + tc * 4], acc2);
        float ol[16];
#pragma unroll
        for (int i = 0; i < 4; i++) {
            float inv = 1.f / (den[tr * 4 + i] + 1e-6f);
            float2 c01 = unpk(acc2[i * 2]), c23 = unpk(acc2[i * 2 + 1]);
            ol[i * 4 + 0] = c01.x * inv; ol[i * 4 + 1] = c01.y * inv;
            ol[i * 4 + 2] = c23.x * inv; ol[i * 4 + 3] = c23.y * inv;
        }
        __syncthreads();
#pragma unroll
        for (int j = 0; j < 4; j++)
            *(float4*)&Pb[(tc * 4 + j) * P68 + tr * 4] =
                make_float4(ol[j], ol[4 + j], ol[8 + j], ol[12 + j]);
    }
    __syncthreads();

    // ---- out = o_s/l + o_l W^T + b (packed) ----
    {
        ull acc2[8];
#pragma unroll
        for (int i = 0; i < 8; i++) acc2[i] = 0ull;
#pragma unroll 16
        for (int e = 0; e < 64; e++)
            GSTEP(&Pb[e * P68 + tr * 4], &WT[e * P68 + tc * 4], acc2);
        float b0 = bl[tc * 4], b1 = bl[tc * 4 + 1], b2 = bl[tc * 4 + 2], b3 = bl[tc * 4 + 3];
#pragma unroll
        for (int i = 0; i < 4; i++) {
            float invl = 1.f / lrow[i];
            float2 s01 = unpk(os2[i * 2]), s23 = unpk(os2[i * 2 + 1]);
            float2 a01 = unpk(acc2[i * 2]), a23 = unpk(acc2[i * 2 + 1]);
            *(float4*)&out[qoff + (size_t)(tr * 4 + i) * 64 + tc * 4] =
                make_float4(s01.x * invl + a01.x + b0,
                            s01.y * invl + a01.y + b1,
                            s23.x * invl + a23.x + b2,
                            s23.y * invl + a23.y + b3);
        }
    }
}

// ---------------------------------------------------------------------------
extern "C" void kernel_launch(void* const* d_in, const int* in_sizes, int n_in,
                              void* d_out, int out_size) {
    const float* q = (const float*)d_in[0];
    const float* k = (const float*)d_in[1];
    const float* v = (const float*)d_in[2];
    const float* W = (const float*)d_in[3];
    const float* b = (const float*)d_in[4];
    float* out = (float*)d_out;

    int smem_main = 26304 * (int)sizeof(float);
    cudaFuncSetAttribute(k_main, cudaFuncAttributeMaxDynamicSharedMemorySize, smem_main);

    dim3 g1(BH * NBLK, 2);
    k_blockmean<<<g1, 64>>>(q, k);
    k_topk<<<BH * NBLK, 64>>>();
    k_kvz<<<BH * NBLK, 256>>>(k, v);
    k_totals<<<dim3(BH, 16), 256>>>();
    k_main<<<BH * NBLK, 256, smem_main>>>(q, k, v, W, b, out);
}